// round 1
// baseline (speedup 1.0000x reference)
#include <cuda_runtime.h>

// Problem constants (fixed shapes from reference)
#define A_TOT 900
#define P_PTS 13
#define NCAMS 6
#define NLVL  4
#define NGRP  8
#define CDIM  256
#define NPN   (P_PTS * NCAMS)        // 78
#define NSAMP (NPN * NLVL)           // 312

// Scratch accumulator (device global — no allocation allowed)
__device__ float g_acc[A_TOT * CDIM];

// ---------------------------------------------------------------------------
// Kernel 1: deformable aggregation.
// One block per anchor; 64 threads; thread t owns channels [4t, 4t+4) (float4).
// Precompute per-sample corner offsets + validity-folded bilinear weights in
// smem, stage the anchor's group-weights in smem, then stream gathers.
// ---------------------------------------------------------------------------
__global__ void __launch_bounds__(64) daf_kernel(
    const float* __restrict__ fm0, const float* __restrict__ fm1,
    const float* __restrict__ fm2, const float* __restrict__ fm3,
    const float* __restrict__ pts, const float* __restrict__ wts)
{
    __shared__ int4   soff[NSAMP];          // corner offsets (float4 units)
    __shared__ float4 swt[NSAMP];           // bilinear corner weights (validity folded)
    __shared__ float  swg[NSAMP * NGRP];    // group weights, layout [s][g]

    const int a = blockIdx.x;
    const int t = threadIdx.x;

    // Stage this anchor's weights: 2496 contiguous floats = 624 float4
    {
        const float4* wsrc = (const float4*)(wts + (size_t)a * NSAMP * NGRP);
        float4* wdst = (float4*)swg;
        #pragma unroll
        for (int i = t; i < (NSAMP * NGRP) / 4; i += 64) wdst[i] = wsrc[i];
    }

    // Precompute per-sample bilinear data
    {
        const float* pbase = pts + (size_t)a * NPN * 2;
        const int Ws[4] = {176, 88, 44, 22};
        const int Hs[4] = {64, 32, 16, 8};
        for (int s = t; s < NSAMP; s += 64) {
            int pn = s >> 2, l = s & 3;
            int n = pn % NCAMS;
            float px = pbase[pn * 2 + 0];
            float py = pbase[pn * 2 + 1];
            int W = Ws[l], H = Hs[l];
            float x = px * (float)W - 0.5f;
            float y = py * (float)H - 0.5f;
            float xf = floorf(x), yf = floorf(y);
            float fx = x - xf, fy = y - yf;
            int x0 = (int)xf, y0 = (int)yf;
            int x1 = x0 + 1, y1 = y0 + 1;
            bool vx0 = (x0 >= 0) && (x0 < W);
            bool vx1 = (x1 >= 0) && (x1 < W);
            bool vy0 = (y0 >= 0) && (y0 < H);
            bool vy1 = (y1 >= 0) && (y1 < H);
            int xc0 = min(max(x0, 0), W - 1);
            int xc1 = min(max(x1, 0), W - 1);
            int yc0 = min(max(y0, 0), H - 1);
            int yc1 = min(max(y1, 0), H - 1);
            int nb = n * H;
            int4 o;
            // offsets in float4 units: pixel * 256 floats / 4 = pixel * 64
            o.x = ((nb + yc0) * W + xc0) * (CDIM / 4);
            o.y = ((nb + yc0) * W + xc1) * (CDIM / 4);
            o.z = ((nb + yc1) * W + xc0) * (CDIM / 4);
            o.w = ((nb + yc1) * W + xc1) * (CDIM / 4);
            soff[s] = o;
            float4 w;
            w.x = (vx0 && vy0) ? (1.f - fx) * (1.f - fy) : 0.f;
            w.y = (vx1 && vy0) ? fx * (1.f - fy) : 0.f;
            w.z = (vx0 && vy1) ? (1.f - fx) * fy : 0.f;
            w.w = (vx1 && vy1) ? fx * fy : 0.f;
            swt[s] = w;
        }
    }
    __syncthreads();

    const float4* const f0 = ((const float4*)fm0) + t;
    const float4* const f1 = ((const float4*)fm1) + t;
    const float4* const f2 = ((const float4*)fm2) + t;
    const float4* const f3 = ((const float4*)fm3) + t;

    const int g = t >> 3;  // group of channels 4t..4t+3
    float4 acc = make_float4(0.f, 0.f, 0.f, 0.f);

    #pragma unroll 2
    for (int pn = 0; pn < NPN; ++pn) {
        const float4* const fms[4] = {f0, f1, f2, f3};
        #pragma unroll
        for (int l = 0; l < 4; ++l) {
            int s = pn * 4 + l;
            int4 o = soff[s];
            float4 w = swt[s];
            float gw = swg[s * NGRP + g];
            const float4* fp = fms[l];
            float4 v00 = __ldg(fp + o.x);
            float4 v10 = __ldg(fp + o.y);
            float4 v01 = __ldg(fp + o.z);
            float4 v11 = __ldg(fp + o.w);
            float wx = w.x * gw, wy = w.y * gw, wz = w.z * gw, ww = w.w * gw;
            acc.x += v00.x * wx + v10.x * wy + v01.x * wz + v11.x * ww;
            acc.y += v00.y * wx + v10.y * wy + v01.y * wz + v11.y * ww;
            acc.z += v00.z * wx + v10.z * wy + v01.z * wz + v11.z * ww;
            acc.w += v00.w * wx + v10.w * wy + v01.w * wz + v11.w * ww;
        }
    }

    ((float4*)(g_acc + (size_t)a * CDIM))[t] = acc;
}

// ---------------------------------------------------------------------------
// Kernel 2: out[a][0:256] = acc[a] @ w_proj + b_proj;  out[a][256:512] = inst[a]
// 6 anchors per block (900 = 150 * 6), 256 threads (one output channel each).
// ---------------------------------------------------------------------------
#define APB 6
__global__ void __launch_bounds__(256) proj_kernel(
    const float* __restrict__ inst, const float* __restrict__ wproj,
    const float* __restrict__ bproj, float* __restrict__ out)
{
    __shared__ float sacc[APB][CDIM];
    const int a0 = blockIdx.x * APB;
    const int c = threadIdx.x;

    #pragma unroll
    for (int i = c; i < APB * CDIM; i += 256)
        ((float*)sacc)[i] = g_acc[(size_t)a0 * CDIM + i];
    __syncthreads();

    float r[APB];
    #pragma unroll
    for (int a = 0; a < APB; ++a) r[a] = 0.f;

    #pragma unroll 4
    for (int k = 0; k < CDIM; ++k) {
        float wv = __ldg(wproj + k * CDIM + c);
        #pragma unroll
        for (int a = 0; a < APB; ++a) r[a] += sacc[a][k] * wv;
    }

    float b = bproj[c];
    #pragma unroll
    for (int a = 0; a < APB; ++a) {
        int aa = a0 + a;
        out[(size_t)aa * 512 + c]       = r[a] + b;
        out[(size_t)aa * 512 + 256 + c] = inst[(size_t)aa * CDIM + c];
    }
}

// ---------------------------------------------------------------------------
extern "C" void kernel_launch(void* const* d_in, const int* in_sizes, int n_in,
                              void* d_out, int out_size)
{
    const float* fm0   = (const float*)d_in[0];
    const float* fm1   = (const float*)d_in[1];
    const float* fm2   = (const float*)d_in[2];
    const float* fm3   = (const float*)d_in[3];
    const float* pts   = (const float*)d_in[4];
    const float* wts   = (const float*)d_in[5];
    const float* inst  = (const float*)d_in[6];
    const float* wproj = (const float*)d_in[7];
    const float* bproj = (const float*)d_in[8];
    float* out = (float*)d_out;

    daf_kernel<<<A_TOT, 64>>>(fm0, fm1, fm2, fm3, pts, wts);
    proj_kernel<<<A_TOT / APB, 256>>>(inst, wproj, bproj, out);
}